// round 7
// baseline (speedup 1.0000x reference)
#include <cuda_runtime.h>
#include <cuda_fp16.h>

#define MAXN 100000
#define MAXE 1600000

// ---------------- scratch (device globals, no allocation allowed) ----------
__device__ __half g_h1h[MAXN * 128];
__device__ float  g_hr[MAXN * 128];
__device__ __half g_h2h[MAXN * 32];
__device__ float  g_as1[MAXN * 4];
__device__ float  g_ad1[MAXN * 4];
__device__ float  g_as2[MAXN];
__device__ float  g_ad2[MAXN];
__device__ int    g_deg[MAXN];
__device__ int    g_off[MAXN + 1];
__device__ int    g_pos[MAXN];
__device__ int    g_ssrc[MAXE];
__device__ int    g_bsum[512];

__device__ __forceinline__ float lrelu(float x) { return x > 0.f ? x : 0.2f * x; }

__device__ __forceinline__ unsigned tf32(float f) {
    unsigned u;
    asm("cvt.rna.tf32.f32 %0, %1;" : "=r"(u) : "f"(f));
    return u;
}

__device__ __forceinline__ void mma_tf32(float* d, const unsigned* a, unsigned b0, unsigned b1) {
    asm volatile(
        "mma.sync.aligned.m16n8k8.row.col.f32.tf32.tf32.f32 "
        "{%0,%1,%2,%3}, {%4,%5,%6,%7}, {%8,%9}, {%0,%1,%2,%3};"
        : "+f"(d[0]), "+f"(d[1]), "+f"(d[2]), "+f"(d[3])
        : "r"(a[0]), "r"(a[1]), "r"(a[2]), "r"(a[3]), "r"(b0), "r"(b1));
}

// ---------------- tf32 tensor-core GEMM: Yh = fp16(X[n,128] @ W[128,nout]) -
// tf32 conversion done at smem store; inner loop reads raw bits.
template <int BN>
__global__ __launch_bounds__(128)
void gemm_tf32(const float* __restrict__ X, const float* __restrict__ W,
               __half* __restrict__ Yh, int n, int nout) {
    constexpr int BM = 128, BK = 32;
    constexpr int NT = BN / 8;
    __shared__ unsigned xs[BM][36];
    __shared__ unsigned ws[BK][72];
    const int tid = threadIdx.x;
    const int warp = tid >> 5;
    const int lane = tid & 31;
    const int g = lane >> 2;
    const int tg = lane & 3;
    const int row0 = blockIdx.x * BM;
    const int col0 = blockIdx.y * BN;
    const int m0 = warp * 32;

    float acc[2][NT][4];
    #pragma unroll
    for (int mi = 0; mi < 2; mi++)
        #pragma unroll
        for (int ni = 0; ni < NT; ni++)
            #pragma unroll
            for (int q = 0; q < 4; q++) acc[mi][ni][q] = 0.f;

    for (int k0 = 0; k0 < 128; k0 += BK) {
        #pragma unroll
        for (int p = 0; p < 8; p++) {
            int idx = p * 128 + tid;
            int r = idx >> 3, q = idx & 7;
            int grow = row0 + r;
            float4 v = make_float4(0.f, 0.f, 0.f, 0.f);
            if (grow < n) v = *(const float4*)&X[grow * 128 + k0 + q * 4];
            xs[r][q * 4 + 0] = tf32(v.x); xs[r][q * 4 + 1] = tf32(v.y);
            xs[r][q * 4 + 2] = tf32(v.z); xs[r][q * 4 + 3] = tf32(v.w);
        }
        #pragma unroll
        for (int idx = tid; idx < BK * BN / 4; idx += 128) {
            int r = idx / (BN / 4), c = idx % (BN / 4);
            float4 v = *(const float4*)&W[(k0 + r) * nout + col0 + c * 4];
            ws[r][c * 4 + 0] = tf32(v.x); ws[r][c * 4 + 1] = tf32(v.y);
            ws[r][c * 4 + 2] = tf32(v.z); ws[r][c * 4 + 3] = tf32(v.w);
        }
        __syncthreads();
        #pragma unroll
        for (int kk = 0; kk < BK; kk += 8) {
            unsigned afrag[2][4];
            #pragma unroll
            for (int mi = 0; mi < 2; mi++) {
                int r = m0 + mi * 16 + g;
                afrag[mi][0] = xs[r][kk + tg];
                afrag[mi][1] = xs[r + 8][kk + tg];
                afrag[mi][2] = xs[r][kk + tg + 4];
                afrag[mi][3] = xs[r + 8][kk + tg + 4];
            }
            #pragma unroll
            for (int ni = 0; ni < NT; ni++) {
                unsigned b0 = ws[kk + tg][ni * 8 + g];
                unsigned b1 = ws[kk + tg + 4][ni * 8 + g];
                mma_tf32(acc[0][ni], afrag[0], b0, b1);
                mma_tf32(acc[1][ni], afrag[1], b0, b1);
            }
        }
        __syncthreads();
    }
    #pragma unroll
    for (int mi = 0; mi < 2; mi++) {
        int ra = row0 + m0 + mi * 16 + g;
        int rb = ra + 8;
        #pragma unroll
        for (int ni = 0; ni < NT; ni++) {
            int c = col0 + ni * 8 + tg * 2;
            if (ra < n)
                *(__half2*)&Yh[ra * nout + c] =
                    __floats2half2_rn(acc[mi][ni][0], acc[mi][ni][1]);
            if (rb < n)
                *(__half2*)&Yh[rb * nout + c] =
                    __floats2half2_rn(acc[mi][ni][2], acc[mi][ni][3]);
        }
    }
}

// ---------------- CSR build --------------------------------------------------
__global__ void hist_kernel(const int* __restrict__ dst, int E, int* __restrict__ deg) {
    int e = blockIdx.x * blockDim.x + threadIdx.x;
    if (e < E) atomicAdd(&deg[dst[e]], 1);
}

__global__ __launch_bounds__(256)
void scan_part(const int* __restrict__ deg, int* __restrict__ bsum, int n) {
    int i = blockIdx.x * 256 + threadIdx.x;
    int v = (i < n) ? deg[i] : 0;
    #pragma unroll
    for (int o = 16; o; o >>= 1) v += __shfl_xor_sync(0xffffffffu, v, o);
    __shared__ int s[8];
    if ((threadIdx.x & 31) == 0) s[threadIdx.x >> 5] = v;
    __syncthreads();
    if (threadIdx.x == 0) {
        int t = 0;
        #pragma unroll
        for (int k = 0; k < 8; k++) t += s[k];
        bsum[blockIdx.x] = t;
    }
}

__global__ __launch_bounds__(512)
void scan_mid(int* __restrict__ bsum, int nb) {
    __shared__ int s[512];
    int t = threadIdx.x;
    int v = (t < nb) ? bsum[t] : 0;
    s[t] = v;
    __syncthreads();
    #pragma unroll
    for (int o = 1; o < 512; o <<= 1) {
        int u = (t >= o) ? s[t - o] : 0;
        __syncthreads();
        s[t] += u;
        __syncthreads();
    }
    if (t < nb) bsum[t] = s[t] - v;
}

__global__ __launch_bounds__(256)
void scan_final(const int* __restrict__ deg, const int* __restrict__ bsum,
                int* __restrict__ off, int* __restrict__ pos, int n) {
    int i = blockIdx.x * 256 + threadIdx.x;
    int lane = threadIdx.x & 31;
    int wid = threadIdx.x >> 5;
    int v = (i < n) ? deg[i] : 0;
    int incl = v;
    #pragma unroll
    for (int o = 1; o < 32; o <<= 1) {
        int u = __shfl_up_sync(0xffffffffu, incl, o);
        if (lane >= o) incl += u;
    }
    __shared__ int wsum[8];
    if (lane == 31) wsum[wid] = incl;
    __syncthreads();
    int wbase = 0;
    #pragma unroll
    for (int k = 0; k < 8; k++) wbase += (k < wid) ? wsum[k] : 0;
    int excl = bsum[blockIdx.x] + wbase + incl - v;
    if (i < n) { off[i] = excl; pos[i] = excl; }
    if (i == n - 1) off[n] = excl + v;
}

__global__ void scatter_kernel(const int* __restrict__ src, const int* __restrict__ dst,
                               int E, int* __restrict__ pos, int* __restrict__ ssrc) {
    int e = blockIdx.x * blockDim.x + threadIdx.x;
    if (e < E) {
        int p = atomicAdd(&pos[dst[e]], 1);
        ssrc[p] = src[e];
    }
}

// -------- node dots (fp16 h): 8 threads per (node,head) group ---------------
template <int H>
__global__ void node_dots(const __half* __restrict__ hh, const float* __restrict__ a_src,
                          const float* __restrict__ a_dst, float* __restrict__ as_,
                          float* __restrict__ ad_, int n) {
    int t = blockIdx.x * blockDim.x + threadIdx.x;
    int g = t >> 3;
    int sub = t & 7;
    if (g >= n * H) return;
    int head = (H == 1) ? 0 : (g & (H - 1));
    uint2 raw = *(const uint2*)&hh[g * 32 + sub * 4];
    float2 f0 = __half22float2(*(__half2*)&raw.x);
    float2 f1 = __half22float2(*(__half2*)&raw.y);
    float4 av = *(const float4*)&a_src[head * 32 + sub * 4];
    float4 dv = *(const float4*)&a_dst[head * 32 + sub * 4];
    float s = f0.x * av.x + f0.y * av.y + f1.x * av.z + f1.y * av.w;
    float d = f0.x * dv.x + f0.y * dv.y + f1.x * dv.z + f1.y * dv.w;
    #pragma unroll
    for (int o = 4; o; o >>= 1) {
        s += __shfl_xor_sync(0xffffffffu, s, o);
        d += __shfl_xor_sync(0xffffffffu, d, o);
    }
    if (sub == 0) { as_[g] = s; ad_[g] = d; }
}

// -------- CSR aggregation, layer 1 (H=4, C=32): one warp per dst ------------
// 8 edges/iter: lane = edge*4 + head -> one full-warp exp per 8 edges.
__global__ __launch_bounds__(256)
void agg4(const int* __restrict__ off, const int* __restrict__ ssrc,
          const __half* __restrict__ hh,
          const float* __restrict__ as_, const float* __restrict__ ad_,
          const float* __restrict__ bias, float* __restrict__ out, int n) {
    int d = (blockIdx.x * blockDim.x + threadIdx.x) >> 5;
    if (d >= n) return;
    const int lane = threadIdx.x & 31;
    const int edge = lane >> 2;       // 0..7
    const int head = lane & 3;        // 0..3
    const int ch = lane * 4;
    const int hsel = lane >> 3;       // head owning this lane's channels

    const float adv = __ldg(&ad_[d * 4 + head]);
    const float asv = __ldg(&as_[d * 4 + head]);

    // self loop: every lane computes its head's self weight (1 warp exp)
    const float wself = __expf(lrelu(asv + adv));
    float den_part = (lane < 4) ? wself : 0.f;   // count once per head

    uint2 rs = *(const uint2*)&hh[d * 128 + ch];
    float2 sa = __half22float2(*(__half2*)&rs.x), sb = __half22float2(*(__half2*)&rs.y);
    const float whs = __shfl_sync(0xffffffffu, wself, hsel);  // lane hsel has head hsel
    float ax = whs * sa.x, ay = whs * sa.y, az = whs * sb.x, aw = whs * sb.y;

    const int end = off[d + 1];
    for (int i = off[d]; i < end; i += 8) {
        const int m = end - i;   // edges this iter (>=1), warp-uniform
        int se = 0;
        if (edge < m) se = __ldg(&ssrc[i + edge]);
        float we = 0.f;
        if (edge < m) we = __expf(lrelu(__ldg(&as_[se * 4 + head]) + adv));
        den_part += we;

        // gather 8 rows first (MLP=8), then weight+accumulate
        uint2 r[8];
        #pragma unroll
        for (int e = 0; e < 8; e++) {
            int s_e = __shfl_sync(0xffffffffu, se, e * 4);
            if (e < m) r[e] = __ldg((const uint2*)&hh[s_e * 128 + ch]);
        }
        #pragma unroll
        for (int e = 0; e < 8; e++) {
            float whe = __shfl_sync(0xffffffffu, we, e * 4 + hsel);
            if (e < m) {
                float2 a = __half22float2(*(__half2*)&r[e].x);
                float2 b = __half22float2(*(__half2*)&r[e].y);
                ax += whe * a.x; ay += whe * a.y;
                az += whe * b.x; aw += whe * b.y;
            }
        }
    }

    // reduce den across the 8 lanes sharing each head
    float den = den_part;
    den += __shfl_xor_sync(0xffffffffu, den, 4);
    den += __shfl_xor_sync(0xffffffffu, den, 8);
    den += __shfl_xor_sync(0xffffffffu, den, 16);
    float inv = 1.f / den;                       // lane L holds inv for head L&3
    float invh = __shfl_sync(0xffffffffu, inv, hsel);

    float4 b = *(const float4*)&bias[ch];
    float4 o;
    o.x = fmaxf(ax * invh + b.x, 0.f);
    o.y = fmaxf(ay * invh + b.y, 0.f);
    o.z = fmaxf(az * invh + b.z, 0.f);
    o.w = fmaxf(aw * invh + b.w, 0.f);
    *(float4*)&out[d * 128 + ch] = o;
}

// -------- CSR aggregation, layer 2 (H=1, C=32): one warp per dst ------------
__global__ __launch_bounds__(256)
void agg1(const int* __restrict__ off, const int* __restrict__ ssrc,
          const __half* __restrict__ hh,
          const float* __restrict__ as_, const float* __restrict__ ad_,
          const float* __restrict__ bias, float* __restrict__ out, int n) {
    int d = (blockIdx.x * blockDim.x + threadIdx.x) >> 5;
    if (d >= n) return;
    const int lane = threadIdx.x & 31;

    const float adv = __ldg(&ad_[d]);                 // broadcast load
    const float wself = __expf(lrelu(__ldg(&as_[d]) + adv));
    float den_part = (lane == 0) ? wself : 0.f;
    float acc = wself * __half2float(hh[d * 32 + lane]);

    const int end = off[d + 1];
    for (int i = off[d]; i < end; i += 8) {
        const int m = end - i;
        int se = 0;
        if (lane < 8 && lane < m) se = __ldg(&ssrc[i + lane]);
        float we = 0.f;
        if (lane < 8 && lane < m) we = __expf(lrelu(__ldg(&as_[se]) + adv));
        den_part += we;

        float hv[8];
        #pragma unroll
        for (int e = 0; e < 8; e++) {
            int s_e = __shfl_sync(0xffffffffu, se, e);
            if (e < m) hv[e] = __half2float(__ldg(&hh[s_e * 32 + lane]));
        }
        #pragma unroll
        for (int e = 0; e < 8; e++) {
            float whe = __shfl_sync(0xffffffffu, we, e);
            if (e < m) acc += whe * hv[e];
        }
    }

    float den = den_part;
    #pragma unroll
    for (int o = 16; o; o >>= 1) den += __shfl_xor_sync(0xffffffffu, den, o);
    float inv = 1.f / den;
    out[d * 32 + lane] = acc * inv + bias[lane];
}

// ---------------------------------------------------------------------------
extern "C" void kernel_launch(void* const* d_in, const int* in_sizes, int n_in,
                              void* d_out, int out_size) {
    const float* x    = (const float*)d_in[0];
    const int*   ei   = (const int*)d_in[1];
    const float* W1   = (const float*)d_in[2];
    const float* asr1 = (const float*)d_in[3];
    const float* adt1 = (const float*)d_in[4];
    const float* b1   = (const float*)d_in[5];
    const float* W2   = (const float*)d_in[6];
    const float* asr2 = (const float*)d_in[7];
    const float* adt2 = (const float*)d_in[8];
    const float* b2   = (const float*)d_in[9];
    float* out = (float*)d_out;

    const int n = in_sizes[0] / 128;
    const int E = in_sizes[1] / 2;
    const int* src = ei;
    const int* dst = ei + E;

    float *hr, *as1, *ad1, *as2, *ad2;
    __half *h1h, *h2h;
    int *deg, *off, *pos, *ssrc, *bsum;
    cudaGetSymbolAddress((void**)&h1h,  g_h1h);
    cudaGetSymbolAddress((void**)&hr,   g_hr);
    cudaGetSymbolAddress((void**)&h2h,  g_h2h);
    cudaGetSymbolAddress((void**)&as1,  g_as1);
    cudaGetSymbolAddress((void**)&ad1,  g_ad1);
    cudaGetSymbolAddress((void**)&as2,  g_as2);
    cudaGetSymbolAddress((void**)&ad2,  g_ad2);
    cudaGetSymbolAddress((void**)&deg,  g_deg);
    cudaGetSymbolAddress((void**)&off,  g_off);
    cudaGetSymbolAddress((void**)&pos,  g_pos);
    cudaGetSymbolAddress((void**)&ssrc, g_ssrc);
    cudaGetSymbolAddress((void**)&bsum, g_bsum);

    static cudaStream_t s2 = nullptr;
    static cudaEvent_t evFork = nullptr, evJoin = nullptr;
    if (!s2) {
        cudaStreamCreateWithFlags(&s2, cudaStreamNonBlocking);
        cudaEventCreateWithFlags(&evFork, cudaEventDisableTiming);
        cudaEventCreateWithFlags(&evJoin, cudaEventDisableTiming);
    }

    const int nb128 = (n + 127) / 128;
    const int eb = (E + 255) / 256;
    const int nwarp_blocks = (n * 32 + 255) / 256;
    const int nscan = (n + 255) / 256;

    // ---- fork: CSR build on side stream ----
    cudaEventRecord(evFork, 0);
    cudaStreamWaitEvent(s2, evFork, 0);
    cudaMemsetAsync(deg, 0, n * sizeof(int), s2);
    hist_kernel<<<eb, 256, 0, s2>>>(dst, E, deg);
    scan_part<<<nscan, 256, 0, s2>>>(deg, bsum, n);
    scan_mid<<<1, 512, 0, s2>>>(bsum, nscan);
    scan_final<<<nscan, 256, 0, s2>>>(deg, bsum, off, pos, n);
    scatter_kernel<<<eb, 256, 0, s2>>>(src, dst, E, pos, ssrc);
    cudaEventRecord(evJoin, s2);

    // ---- main stream: layer-1 GEMM + dots ----
    gemm_tf32<64><<<dim3(nb128, 2), 128>>>(x, W1, h1h, n, 128);
    node_dots<4><<<(n * 4 * 8 + 255) / 256, 256>>>(h1h, asr1, adt1, as1, ad1, n);

    // ---- join ----
    cudaStreamWaitEvent(0, evJoin, 0);
    agg4<<<nwarp_blocks, 256>>>(off, ssrc, h1h, as1, ad1, b1, hr, n);

    // ---- Layer 2 ----
    gemm_tf32<32><<<dim3(nb128, 1), 128>>>(hr, W2, h2h, n, 32);
    node_dots<1><<<(n * 8 + 255) / 256, 256>>>(h2h, asr2, adt2, as2, ad2, n);
    agg1<<<nwarp_blocks, 256>>>(off, ssrc, h2h, as2, ad2, b2, out, n);
}

// round 8
// speedup vs baseline: 1.1367x; 1.1367x over previous
#include <cuda_runtime.h>
#include <cuda_fp16.h>

#define MAXN 100000
#define MAXE 1600000

// ---------------- scratch (device globals, no allocation allowed) ----------
__device__ __half g_h1h[MAXN * 128];
__device__ float  g_hr[MAXN * 128];
__device__ __half g_h2h[MAXN * 32];
__device__ float  g_as1[MAXN * 4];
__device__ float  g_ad1[MAXN * 4];
__device__ float  g_as2[MAXN];
__device__ float  g_ad2[MAXN];
__device__ int    g_deg[MAXN];
__device__ int    g_off[MAXN + 1];
__device__ int    g_pos[MAXN];
__device__ int    g_ssrc[MAXE];
__device__ int    g_bsum[512];

__device__ __forceinline__ float lrelu(float x) { return x > 0.f ? x : 0.2f * x; }

__device__ __forceinline__ unsigned tf32(float f) {
    unsigned u;
    asm("cvt.rna.tf32.f32 %0, %1;" : "=r"(u) : "f"(f));
    return u;
}

__device__ __forceinline__ void mma_tf32(float* d, const unsigned* a, unsigned b0, unsigned b1) {
    asm volatile(
        "mma.sync.aligned.m16n8k8.row.col.f32.tf32.tf32.f32 "
        "{%0,%1,%2,%3}, {%4,%5,%6,%7}, {%8,%9}, {%0,%1,%2,%3};"
        : "+f"(d[0]), "+f"(d[1]), "+f"(d[2]), "+f"(d[3])
        : "r"(a[0]), "r"(a[1]), "r"(a[2]), "r"(a[3]), "r"(b0), "r"(b1));
}

// ---------------- tf32 tensor-core GEMM + fused attention dots -------------
// Yh = fp16(X[n,128] @ W[128,nout]); also writes as_[row*HT+head], ad_ from
// the fp32 accumulators (head = col/32, complete heads per block).
template <int BN, int HT>
__global__ __launch_bounds__(128)
void gemm_tf32(const float* __restrict__ X, const float* __restrict__ W,
               __half* __restrict__ Yh,
               const float* __restrict__ a_src, const float* __restrict__ a_dst,
               float* __restrict__ as_, float* __restrict__ ad_,
               int n, int nout) {
    constexpr int BM = 128, BK = 32;
    constexpr int NT = BN / 8;
    constexpr int NHEAD = BN / 32;          // heads per block (2 or 1)
    __shared__ unsigned xs[BM][36];
    __shared__ unsigned ws[BK][72];
    __shared__ float s_asrc[BN], s_adst[BN];
    const int tid = threadIdx.x;
    const int warp = tid >> 5;
    const int lane = tid & 31;
    const int g = lane >> 2;
    const int tg = lane & 3;
    const int row0 = blockIdx.x * BM;
    const int col0 = blockIdx.y * BN;
    const int m0 = warp * 32;

    if (tid < BN) {
        s_asrc[tid] = a_src[col0 + tid];
        s_adst[tid] = a_dst[col0 + tid];
    }

    float acc[2][NT][4];
    #pragma unroll
    for (int mi = 0; mi < 2; mi++)
        #pragma unroll
        for (int ni = 0; ni < NT; ni++)
            #pragma unroll
            for (int q = 0; q < 4; q++) acc[mi][ni][q] = 0.f;

    for (int k0 = 0; k0 < 128; k0 += BK) {
        #pragma unroll
        for (int p = 0; p < 8; p++) {
            int idx = p * 128 + tid;
            int r = idx >> 3, q = idx & 7;
            int grow = row0 + r;
            float4 v = make_float4(0.f, 0.f, 0.f, 0.f);
            if (grow < n) v = *(const float4*)&X[grow * 128 + k0 + q * 4];
            xs[r][q * 4 + 0] = tf32(v.x); xs[r][q * 4 + 1] = tf32(v.y);
            xs[r][q * 4 + 2] = tf32(v.z); xs[r][q * 4 + 3] = tf32(v.w);
        }
        #pragma unroll
        for (int idx = tid; idx < BK * BN / 4; idx += 128) {
            int r = idx / (BN / 4), c = idx % (BN / 4);
            float4 v = *(const float4*)&W[(k0 + r) * nout + col0 + c * 4];
            ws[r][c * 4 + 0] = tf32(v.x); ws[r][c * 4 + 1] = tf32(v.y);
            ws[r][c * 4 + 2] = tf32(v.z); ws[r][c * 4 + 3] = tf32(v.w);
        }
        __syncthreads();
        #pragma unroll
        for (int kk = 0; kk < BK; kk += 8) {
            unsigned afrag[2][4];
            #pragma unroll
            for (int mi = 0; mi < 2; mi++) {
                int r = m0 + mi * 16 + g;
                afrag[mi][0] = xs[r][kk + tg];
                afrag[mi][1] = xs[r + 8][kk + tg];
                afrag[mi][2] = xs[r][kk + tg + 4];
                afrag[mi][3] = xs[r + 8][kk + tg + 4];
            }
            #pragma unroll
            for (int ni = 0; ni < NT; ni++) {
                unsigned b0 = ws[kk + tg][ni * 8 + g];
                unsigned b1 = ws[kk + tg + 4][ni * 8 + g];
                mma_tf32(acc[0][ni], afrag[0], b0, b1);
                mma_tf32(acc[1][ni], afrag[1], b0, b1);
            }
        }
        __syncthreads();
    }

    const int hd0 = col0 / 32;   // first head this block owns
    #pragma unroll
    for (int mi = 0; mi < 2; mi++) {
        #pragma unroll
        for (int half = 0; half < 2; half++) {     // half=0: row ra(+g), 1: rb(+g+8)
            int row = row0 + m0 + mi * 16 + g + half * 8;
            // dot partials for this row (per head), over this thread's 2*NT cols
            float sv[NHEAD], dv[NHEAD];
            #pragma unroll
            for (int h = 0; h < NHEAD; h++) { sv[h] = 0.f; dv[h] = 0.f; }
            #pragma unroll
            for (int ni = 0; ni < NT; ni++) {
                int j = ni * 8 + tg * 2;
                float va = acc[mi][ni][half * 2 + 0];
                float vb = acc[mi][ni][half * 2 + 1];
                int h = (NHEAD == 1) ? 0 : (ni / (NT / 2));
                sv[h] += va * s_asrc[j] + vb * s_asrc[j + 1];
                dv[h] += va * s_adst[j] + vb * s_adst[j + 1];
            }
            // reduce over the tg-quad (lanes sharing g)
            #pragma unroll
            for (int h = 0; h < NHEAD; h++) {
                sv[h] += __shfl_xor_sync(0xffffffffu, sv[h], 1);
                sv[h] += __shfl_xor_sync(0xffffffffu, sv[h], 2);
                dv[h] += __shfl_xor_sync(0xffffffffu, dv[h], 1);
                dv[h] += __shfl_xor_sync(0xffffffffu, dv[h], 2);
            }
            if (row < n) {
                if (tg == 0) {
                    #pragma unroll
                    for (int h = 0; h < NHEAD; h++) {
                        as_[row * HT + hd0 + h] = sv[h];
                        ad_[row * HT + hd0 + h] = dv[h];
                    }
                }
                int c = row * nout + col0 + tg * 2;
                #pragma unroll
                for (int ni = 0; ni < NT; ni++)
                    *(__half2*)&Yh[c + ni * 8] =
                        __floats2half2_rn(acc[mi][ni][half * 2], acc[mi][ni][half * 2 + 1]);
            }
        }
    }
}

// ---------------- CSR build --------------------------------------------------
__global__ void hist_kernel(const int* __restrict__ dst, int E, int* __restrict__ deg) {
    int e = blockIdx.x * blockDim.x + threadIdx.x;
    if (e < E) atomicAdd(&deg[dst[e]], 1);
}

__global__ __launch_bounds__(256)
void scan_part(const int* __restrict__ deg, int* __restrict__ bsum, int n) {
    int i = blockIdx.x * 256 + threadIdx.x;
    int v = (i < n) ? deg[i] : 0;
    #pragma unroll
    for (int o = 16; o; o >>= 1) v += __shfl_xor_sync(0xffffffffu, v, o);
    __shared__ int s[8];
    if ((threadIdx.x & 31) == 0) s[threadIdx.x >> 5] = v;
    __syncthreads();
    if (threadIdx.x == 0) {
        int t = 0;
        #pragma unroll
        for (int k = 0; k < 8; k++) t += s[k];
        bsum[blockIdx.x] = t;
    }
}

__global__ __launch_bounds__(512)
void scan_mid(int* __restrict__ bsum, int nb) {
    __shared__ int s[512];
    int t = threadIdx.x;
    int v = (t < nb) ? bsum[t] : 0;
    s[t] = v;
    __syncthreads();
    #pragma unroll
    for (int o = 1; o < 512; o <<= 1) {
        int u = (t >= o) ? s[t - o] : 0;
        __syncthreads();
        s[t] += u;
        __syncthreads();
    }
    if (t < nb) bsum[t] = s[t] - v;
}

__global__ __launch_bounds__(256)
void scan_final(const int* __restrict__ deg, const int* __restrict__ bsum,
                int* __restrict__ off, int* __restrict__ pos, int n) {
    int i = blockIdx.x * 256 + threadIdx.x;
    int lane = threadIdx.x & 31;
    int wid = threadIdx.x >> 5;
    int v = (i < n) ? deg[i] : 0;
    int incl = v;
    #pragma unroll
    for (int o = 1; o < 32; o <<= 1) {
        int u = __shfl_up_sync(0xffffffffu, incl, o);
        if (lane >= o) incl += u;
    }
    __shared__ int wsum[8];
    if (lane == 31) wsum[wid] = incl;
    __syncthreads();
    int wbase = 0;
    #pragma unroll
    for (int k = 0; k < 8; k++) wbase += (k < wid) ? wsum[k] : 0;
    int excl = bsum[blockIdx.x] + wbase + incl - v;
    if (i < n) { off[i] = excl; pos[i] = excl; }
    if (i == n - 1) off[n] = excl + v;
}

__global__ void scatter_kernel(const int* __restrict__ src, const int* __restrict__ dst,
                               int E, int* __restrict__ pos, int* __restrict__ ssrc) {
    int e = blockIdx.x * blockDim.x + threadIdx.x;
    if (e < E) {
        int p = atomicAdd(&pos[dst[e]], 1);
        ssrc[p] = src[e];
    }
}

// -------- CSR aggregation, layer 1 (H=4, C=32): one warp per dst ------------
// 4 edges/iter, exp distributed over 16 lanes (lane = edge*4 + head).
__global__ __launch_bounds__(256)
void agg4(const int* __restrict__ off, const int* __restrict__ ssrc,
          const __half* __restrict__ hh,
          const float* __restrict__ as_, const float* __restrict__ ad_,
          const float* __restrict__ bias, float* __restrict__ out, int n) {
    int d = (blockIdx.x * blockDim.x + threadIdx.x) >> 5;
    if (d >= n) return;
    int lane = threadIdx.x & 31;
    int ch = lane * 4;
    int hsel = lane >> 3;

    float adv = 0.f, asv = 0.f;
    if (lane < 4) { adv = ad_[d * 4 + lane]; asv = as_[d * 4 + lane]; }
    float advl = __shfl_sync(0xffffffffu, adv, lane & 3);  // adv for head lane&3

    // self loop
    uint2 rs = *(const uint2*)&hh[d * 128 + ch];
    float2 sa = __half22float2(*(__half2*)&rs.x), sb = __half22float2(*(__half2*)&rs.y);
    float w = 0.f, den = 0.f;
    if (lane < 4) { w = __expf(lrelu(asv + adv)); den = w; }
    float wh = __shfl_sync(0xffffffffu, w, hsel);
    float ax = wh * sa.x, ay = wh * sa.y, az = wh * sb.x, aw = wh * sb.y;

    int i = off[d], end = off[d + 1];
    for (; i + 3 < end; i += 4) {
        int s0 = __ldg(&ssrc[i]);
        int s1 = __ldg(&ssrc[i + 1]);
        int s2 = __ldg(&ssrc[i + 2]);
        int s3 = __ldg(&ssrc[i + 3]);
        uint2 r0 = __ldg((const uint2*)&hh[s0 * 128 + ch]);
        uint2 r1 = __ldg((const uint2*)&hh[s1 * 128 + ch]);
        uint2 r2 = __ldg((const uint2*)&hh[s2 * 128 + ch]);
        uint2 r3 = __ldg((const uint2*)&hh[s3 * 128 + ch]);
        // lanes 0..15: edge = lane>>2, head = lane&3
        float we = 0.f;
        if (lane < 16) {
            int e = lane >> 2;
            int se = (e == 0) ? s0 : (e == 1) ? s1 : (e == 2) ? s2 : s3;
            float av = __ldg(&as_[se * 4 + (lane & 3)]);
            we = __expf(lrelu(av + advl));
        }
        // per-head denominator sums (lanes 0..3 end up with totals)
        float wsum = we + __shfl_xor_sync(0xffffffffu, we, 4);
        wsum += __shfl_xor_sync(0xffffffffu, wsum, 8);
        if (lane < 4) den += wsum;
        // per-edge weight for this lane's head
        float wh0 = __shfl_sync(0xffffffffu, we, 0 + hsel);
        float wh1 = __shfl_sync(0xffffffffu, we, 4 + hsel);
        float wh2 = __shfl_sync(0xffffffffu, we, 8 + hsel);
        float wh3 = __shfl_sync(0xffffffffu, we, 12 + hsel);
        float2 a0 = __half22float2(*(__half2*)&r0.x), b0 = __half22float2(*(__half2*)&r0.y);
        float2 a1 = __half22float2(*(__half2*)&r1.x), b1 = __half22float2(*(__half2*)&r1.y);
        float2 a2 = __half22float2(*(__half2*)&r2.x), b2 = __half22float2(*(__half2*)&r2.y);
        float2 a3 = __half22float2(*(__half2*)&r3.x), b3 = __half22float2(*(__half2*)&r3.y);
        ax += wh0 * a0.x + wh1 * a1.x + wh2 * a2.x + wh3 * a3.x;
        ay += wh0 * a0.y + wh1 * a1.y + wh2 * a2.y + wh3 * a3.y;
        az += wh0 * b0.x + wh1 * b1.x + wh2 * b2.x + wh3 * b3.x;
        aw += wh0 * b0.y + wh1 * b1.y + wh2 * b2.y + wh3 * b3.y;
    }
    for (; i < end; i++) {
        int s0 = __ldg(&ssrc[i]);
        uint2 r0 = __ldg((const uint2*)&hh[s0 * 128 + ch]);
        float w0 = 0.f;
        if (lane < 4) {
            w0 = __expf(lrelu(__ldg(&as_[s0 * 4 + lane]) + adv));
            den += w0;
        }
        float wh0 = __shfl_sync(0xffffffffu, w0, hsel);
        float2 a0 = __half22float2(*(__half2*)&r0.x), b0 = __half22float2(*(__half2*)&r0.y);
        ax += wh0 * a0.x; ay += wh0 * a0.y; az += wh0 * b0.x; aw += wh0 * b0.y;
    }

    float inv = (lane < 4) ? 1.f / den : 0.f;
    float invh = __shfl_sync(0xffffffffu, inv, hsel);
    float4 b = *(const float4*)&bias[ch];
    float4 o;
    o.x = fmaxf(ax * invh + b.x, 0.f);
    o.y = fmaxf(ay * invh + b.y, 0.f);
    o.z = fmaxf(az * invh + b.z, 0.f);
    o.w = fmaxf(aw * invh + b.w, 0.f);
    *(float4*)&out[d * 128 + ch] = o;
}

// -------- CSR aggregation, layer 2 (H=1, C=32): one warp per dst ------------
__global__ __launch_bounds__(256)
void agg1(const int* __restrict__ off, const int* __restrict__ ssrc,
          const __half* __restrict__ hh,
          const float* __restrict__ as_, const float* __restrict__ ad_,
          const float* __restrict__ bias, float* __restrict__ out, int n) {
    int d = (blockIdx.x * blockDim.x + threadIdx.x) >> 5;
    if (d >= n) return;
    int lane = threadIdx.x & 31;

    float adv = 0.f;
    if (lane == 0) adv = ad_[d];
    adv = __shfl_sync(0xffffffffu, adv, 0);

    float w = 0.f, den = 0.f;
    if (lane == 0) { w = __expf(lrelu(as_[d] + adv)); den = w; }
    float wb = __shfl_sync(0xffffffffu, w, 0);
    float acc = wb * __half2float(hh[d * 32 + lane]);

    int i = off[d], end = off[d + 1];
    for (; i + 3 < end; i += 4) {
        int s0 = __ldg(&ssrc[i]);
        int s1 = __ldg(&ssrc[i + 1]);
        int s2 = __ldg(&ssrc[i + 2]);
        int s3 = __ldg(&ssrc[i + 3]);
        float h0 = __half2float(__ldg(&hh[s0 * 32 + lane]));
        float h1 = __half2float(__ldg(&hh[s1 * 32 + lane]));
        float h2 = __half2float(__ldg(&hh[s2 * 32 + lane]));
        float h3 = __half2float(__ldg(&hh[s3 * 32 + lane]));
        float we = 0.f;
        if (lane < 4) {
            int se = (lane == 0) ? s0 : (lane == 1) ? s1 : (lane == 2) ? s2 : s3;
            we = __expf(lrelu(__ldg(&as_[se]) + adv));
        }
        float wsum = we + __shfl_xor_sync(0xffffffffu, we, 1);
        wsum += __shfl_xor_sync(0xffffffffu, wsum, 2);
        if (lane == 0) den += wsum;
        float w0 = __shfl_sync(0xffffffffu, we, 0);
        float w1 = __shfl_sync(0xffffffffu, we, 1);
        float w2 = __shfl_sync(0xffffffffu, we, 2);
        float w3 = __shfl_sync(0xffffffffu, we, 3);
        acc += w0 * h0 + w1 * h1 + w2 * h2 + w3 * h3;
    }
    for (; i < end; i++) {
        int s0 = __ldg(&ssrc[i]);
        float h0 = __half2float(__ldg(&hh[s0 * 32 + lane]));
        float w0 = 0.f;
        if (lane == 0) {
            w0 = __expf(lrelu(__ldg(&as_[s0]) + adv));
            den += w0;
        }
        w0 = __shfl_sync(0xffffffffu, w0, 0);
        acc += w0 * h0;
    }

    float inv = 0.f;
    if (lane == 0) inv = 1.f / den;
    inv = __shfl_sync(0xffffffffu, inv, 0);
    out[d * 32 + lane] = acc * inv + bias[lane];
}

// ---------------------------------------------------------------------------
extern "C" void kernel_launch(void* const* d_in, const int* in_sizes, int n_in,
                              void* d_out, int out_size) {
    const float* x    = (const float*)d_in[0];
    const int*   ei   = (const int*)d_in[1];
    const float* W1   = (const float*)d_in[2];
    const float* asr1 = (const float*)d_in[3];
    const float* adt1 = (const float*)d_in[4];
    const float* b1   = (const float*)d_in[5];
    const float* W2   = (const float*)d_in[6];
    const float* asr2 = (const float*)d_in[7];
    const float* adt2 = (const float*)d_in[8];
    const float* b2   = (const float*)d_in[9];
    float* out = (float*)d_out;

    const int n = in_sizes[0] / 128;
    const int E = in_sizes[1] / 2;
    const int* src = ei;
    const int* dst = ei + E;

    float *hr, *as1, *ad1, *as2, *ad2;
    __half *h1h, *h2h;
    int *deg, *off, *pos, *ssrc, *bsum;
    cudaGetSymbolAddress((void**)&h1h,  g_h1h);
    cudaGetSymbolAddress((void**)&hr,   g_hr);
    cudaGetSymbolAddress((void**)&h2h,  g_h2h);
    cudaGetSymbolAddress((void**)&as1,  g_as1);
    cudaGetSymbolAddress((void**)&ad1,  g_ad1);
    cudaGetSymbolAddress((void**)&as2,  g_as2);
    cudaGetSymbolAddress((void**)&ad2,  g_ad2);
    cudaGetSymbolAddress((void**)&deg,  g_deg);
    cudaGetSymbolAddress((void**)&off,  g_off);
    cudaGetSymbolAddress((void**)&pos,  g_pos);
    cudaGetSymbolAddress((void**)&ssrc, g_ssrc);
    cudaGetSymbolAddress((void**)&bsum, g_bsum);

    static cudaStream_t s2 = nullptr;
    static cudaEvent_t evFork = nullptr, evJoin = nullptr;
    if (!s2) {
        cudaStreamCreateWithFlags(&s2, cudaStreamNonBlocking);
        cudaEventCreateWithFlags(&evFork, cudaEventDisableTiming);
        cudaEventCreateWithFlags(&evJoin, cudaEventDisableTiming);
    }

    const int nb128 = (n + 127) / 128;
    const int eb = (E + 255) / 256;
    const int nwarp_blocks = (n * 32 + 255) / 256;
    const int nscan = (n + 255) / 256;

    // ---- fork: CSR build on side stream ----
    cudaEventRecord(evFork, 0);
    cudaStreamWaitEvent(s2, evFork, 0);
    cudaMemsetAsync(deg, 0, n * sizeof(int), s2);
    hist_kernel<<<eb, 256, 0, s2>>>(dst, E, deg);
    scan_part<<<nscan, 256, 0, s2>>>(deg, bsum, n);
    scan_mid<<<1, 512, 0, s2>>>(bsum, nscan);
    scan_final<<<nscan, 256, 0, s2>>>(deg, bsum, off, pos, n);
    scatter_kernel<<<eb, 256, 0, s2>>>(src, dst, E, pos, ssrc);
    cudaEventRecord(evJoin, s2);

    // ---- main stream: layer-1 GEMM (+fused dots) ----
    gemm_tf32<64, 4><<<dim3(nb128, 2), 128>>>(x, W1, h1h, asr1, adt1, as1, ad1, n, 128);

    // ---- join ----
    cudaStreamWaitEvent(0, evJoin, 0);
    agg4<<<nwarp_blocks, 256>>>(off, ssrc, h1h, as1, ad1, b1, hr, n);

    // ---- Layer 2 ----
    gemm_tf32<32, 1><<<dim3(nb128, 1), 128>>>(hr, W2, h2h, asr2, adt2, as2, ad2, n, 32);
    agg1<<<nwarp_blocks, 256>>>(off, ssrc, h2h, as2, ad2, b2, out, n);
}